// round 7
// baseline (speedup 1.0000x reference)
#include <cuda_runtime.h>
#include <cuda.h>

typedef unsigned int u32;
typedef unsigned long long u64;
typedef signed char i8;

#define BB 4
#define SS 2048
#define EE 1024
#define HH 16
#define DD 64
#define QQ 4
#define MM (BB*SS)   /* 8192 tokens */

// ───────── scratch (allocation-free rule: __device__ globals) ─────────
__device__ float g_q[(size_t)MM * (QQ*EE)];
__device__ float g_k[(size_t)MM * EE];
__device__ float g_v[(size_t)MM * EE];
__device__ float g_z[(size_t)MM * EE];

__device__ i8 g_xhi[(size_t)MM*EE],  g_xlo[(size_t)MM*EE];
__device__ i8 g_zhi[(size_t)MM*EE],  g_zlo[(size_t)MM*EE];
__device__ i8 g_wqhi[(size_t)QQ*EE*EE], g_wqlo[(size_t)QQ*EE*EE];
__device__ i8 g_wkhi[(size_t)EE*EE], g_wklo[(size_t)EE*EE];
__device__ i8 g_wvhi[(size_t)EE*EE], g_wvlo[(size_t)EE*EE];
__device__ i8 g_wohi[(size_t)EE*EE], g_wolo[(size_t)EE*EE];
__device__ float g_sx[MM], g_sz[MM];
__device__ float g_swq[QQ*EE], g_swk[EE], g_swv[EE], g_swo[EE];

__device__ __forceinline__ u32 smem_u32(const void* p) {
    u32 a;
    asm("{ .reg .u64 t; cvta.to.shared.u64 t, %1; cvt.u32.u64 %0, t; }"
        : "=r"(a) : "l"(p));
    return a;
}
__device__ __forceinline__ void ldsm4(u32 addr, u32* r) {
    asm volatile("ldmatrix.sync.aligned.m8n8.x4.shared.b16 {%0,%1,%2,%3}, [%4];"
                 : "=r"(r[0]), "=r"(r[1]), "=r"(r[2]), "=r"(r[3]) : "r"(addr));
}
__device__ __forceinline__ void mmai8(int* c, const u32* a, const u32* b) {
    asm volatile(
        "mma.sync.aligned.m16n8k32.row.col.s32.s8.s8.s32 "
        "{%0,%1,%2,%3}, {%4,%5,%6,%7}, {%8,%9}, {%0,%1,%2,%3};"
        : "+r"(c[0]), "+r"(c[1]), "+r"(c[2]), "+r"(c[3])
        : "r"(a[0]), "r"(a[1]), "r"(a[2]), "r"(a[3]), "r"(b[0]), "r"(b[1]));
}
__device__ __forceinline__ void tma2d(u32 saddr, const CUtensorMap* m,
                                      int cx, int cy, u32 mbar) {
    asm volatile(
        "cp.async.bulk.tensor.2d.shared::cta.global.tile.mbarrier::complete_tx::bytes "
        "[%0], [%1, {%2, %3}], [%4];"
        :: "r"(saddr), "l"(m), "r"(cx), "r"(cy), "r"(mbar) : "memory");
}
#define MBAR_INIT(addr, cnt) \
    asm volatile("mbarrier.init.shared.b64 [%0], %1;" :: "r"(addr), "r"(cnt) : "memory")
#define MBAR_EXPECT(addr, bytes) \
    asm volatile("mbarrier.arrive.expect_tx.shared.b64 _, [%0], %1;" \
                 :: "r"(addr), "r"(bytes) : "memory")
__device__ __forceinline__ void mbar_wait(u32 addr, u32 parity) {
    asm volatile(
        "{\n\t.reg .pred P;\n\t"
        "W%=:\n\t"
        "mbarrier.try_wait.parity.acquire.cta.shared::cta.b64 P, [%0], %1, 0x989680;\n\t"
        "@P bra D%=;\n\t"
        "bra W%=;\n\t"
        "D%=:\n\t}"
        :: "r"(addr), "r"(parity) : "memory");
}
#define SWZ(off) ((u32)(off) ^ ((((u32)(off)) >> 3) & 0x70))

// ───────── per-row 2-slice int8 quantization: v = s·(128·h + l) ─────────
__global__ __launch_bounds__(256) void rowquant(
    const float* __restrict__ src, i8* __restrict__ hi, i8* __restrict__ lo,
    float* __restrict__ scale)
{
    const int row = blockIdx.x, tid = threadIdx.x;
    const float4* r4 = (const float4*)(src + (size_t)row * EE);
    float4 v = r4[tid];                       // EE/4 = 256 = blockDim
    float m = fmaxf(fmaxf(fabsf(v.x), fabsf(v.y)), fmaxf(fabsf(v.z), fabsf(v.w)));
    #pragma unroll
    for (int o = 16; o; o >>= 1) m = fmaxf(m, __shfl_xor_sync(~0u, m, o));
    __shared__ float red[8];
    if ((tid & 31) == 0) red[tid >> 5] = m;
    __syncthreads();
    float am = red[0];
    #pragma unroll
    for (int i = 1; i < 8; i++) am = fmaxf(am, red[i]);
    const float s = fmaxf(am, 1e-30f) * (1.0f / 16256.0f);
    if (tid == 0) scale[row] = s;
    const float inv = 1.0f / s;
    float f[4] = {v.x, v.y, v.z, v.w};
    i8 hb[4], lb[4];
    #pragma unroll
    for (int j = 0; j < 4; j++) {
        float u  = f[j] * inv;                 // |u| ≤ 16256
        float hh = rintf(u * (1.0f / 128.0f)); // ∈ [-127, 127]
        float ll = rintf(u - hh * 128.0f);     // ∈ [-64, 64]
        hb[j] = (i8)hh;
        lb[j] = (i8)ll;
    }
    ((char4*)hi)[(size_t)row * 256 + tid] = make_char4(hb[0], hb[1], hb[2], hb[3]);
    ((char4*)lo)[(size_t)row * 256 + tid] = make_char4(lb[0], lb[1], lb[2], lb[3]);
}

// ───────── int8 2-slice GEMM: TMA + mma.sync.m16n8k32 ─────────
// C[m,n] = s_a[m]·s_b[n]·(16384·Σ h_a·h_b + 128·Σ(h_a·l_b + l_a·h_b)) + bias[n]
// CTA tile 128×256, 16 warps × (64m×32n), K-chunk 128 bytes, 2-stage TMA.
#define SOFF_AH 0u
#define SOFF_AL 16384u
#define SOFF_BH 32768u
#define SOFF_BL 65536u
#define STB 98304u
#define SM_CTRL (2u*STB)
#define GSMEM (2*98304 + 64)

__global__ __launch_bounds__(512, 1) void igemm(
    const __grid_constant__ CUtensorMap tAh,
    const __grid_constant__ CUtensorMap tAl,
    const __grid_constant__ CUtensorMap tBh,
    const __grid_constant__ CUtensorMap tBl,
    const float* __restrict__ sa, const float* __restrict__ sb,
    const float* __restrict__ bias, float* __restrict__ C,
    int M, int N_, int K)
{
    extern __shared__ __align__(1024) char smem[];
    const u32 sb_  = smem_u32(smem);
    const int tid  = threadIdx.x;
    const int wid  = tid >> 5;
    const int lane = tid & 31;
    const int m0   = blockIdx.y * 128;
    const int n0   = blockIdx.x * 256;
    const int wm   = (wid & 1) * 64;      // 2 m-slices of 64
    const int wn   = (wid >> 1) * 32;     // 8 n-slices of 32
    const int nch  = K / 128;             // 8

    int accA[4][4][4], accB[4][4][4];     // [ma][n8-slot][frag]
    #pragma unroll
    for (int i = 0; i < 4; i++)
        #pragma unroll
        for (int j = 0; j < 4; j++)
            #pragma unroll
            for (int t = 0; t < 4; t++) { accA[i][j][t] = 0; accB[i][j][t] = 0; }

    if (tid == 0) { MBAR_INIT(sb_ + SM_CTRL, 1); MBAR_INIT(sb_ + SM_CTRL + 8, 1); }
    __syncthreads();

    auto issue = [&](int c) {
        if (tid == 0) {
            const u32 mbar = sb_ + SM_CTRL + (c & 1) * 8;
            const u32 s0   = sb_ + (c & 1) * STB;
            MBAR_EXPECT(mbar, 98304u);
            int kc = c * 128;              // byte coord in K
            tma2d(s0 + SOFF_AH, &tAh, kc, m0, mbar);
            tma2d(s0 + SOFF_AL, &tAl, kc, m0, mbar);
            tma2d(s0 + SOFF_BH, &tBh, kc, n0, mbar);
            tma2d(s0 + SOFF_BL, &tBl, kc, n0, mbar);
        }
    };

    issue(0);
    issue(1);

    for (int c = 0; c < nch; c++) {
        mbar_wait(sb_ + SM_CTRL + (c & 1) * 8, (c >> 1) & 1);
        const u32 s0 = sb_ + (c & 1) * STB;

        #pragma unroll
        for (int ks = 0; ks < 4; ks++) {           // 4 × 32 k-bytes
            const int kb = ks * 32;
            u32 ah[4][4], al[4][4];
            #pragma unroll
            for (int ma = 0; ma < 4; ma++) {
                int row = wm + ma * 16 + ((lane >> 3) & 1) * 8 + (lane & 7);
                int cb  = kb + (lane >> 4) * 16;
                u32 off = SWZ(row * 128 + cb);
                ldsm4(s0 + SOFF_AH + off, ah[ma]);
                ldsm4(s0 + SOFF_AL + off, al[ma]);
            }
            #pragma unroll
            for (int j = 0; j < 2; j++) {          // 2 × 16-n tiles
                u32 bh[4], bl[4];
                int row = wn + j * 16 + (lane >> 4) * 8 + (lane & 7);
                int cb  = kb + ((lane >> 3) & 1) * 16;
                u32 off = SWZ(row * 128 + cb);
                ldsm4(s0 + SOFF_BH + off, bh);
                ldsm4(s0 + SOFF_BL + off, bl);
                // pass hh → accA ; passes hl, lh → accB
                #pragma unroll
                for (int ma = 0; ma < 4; ma++) {
                    mmai8(accA[ma][j*2+0], ah[ma], &bh[0]);
                    mmai8(accA[ma][j*2+1], ah[ma], &bh[2]);
                }
                #pragma unroll
                for (int ma = 0; ma < 4; ma++) {
                    mmai8(accB[ma][j*2+0], ah[ma], &bl[0]);
                    mmai8(accB[ma][j*2+1], ah[ma], &bl[2]);
                }
                #pragma unroll
                for (int ma = 0; ma < 4; ma++) {
                    mmai8(accB[ma][j*2+0], al[ma], &bh[0]);
                    mmai8(accB[ma][j*2+1], al[ma], &bh[2]);
                }
            }
        }
        __syncthreads();
        if (c + 2 < nch) issue(c + 2);
    }

    // epilogue: dequant + bias
    #pragma unroll
    for (int ma = 0; ma < 4; ma++) {
        int r0 = m0 + wm + ma * 16 + (lane >> 2);
        float sa0 = sa[r0], sa1 = sa[r0 + 8];
        #pragma unroll
        for (int nb = 0; nb < 4; nb++) {
            int col = n0 + wn + nb * 8 + (lane & 3) * 2;
            float sb0 = sb[col], sb1 = sb[col + 1];
            float b0 = bias[col], b1 = bias[col + 1];
            float v00 = 16384.f * (float)accA[ma][nb][0] + 128.f * (float)accB[ma][nb][0];
            float v01 = 16384.f * (float)accA[ma][nb][1] + 128.f * (float)accB[ma][nb][1];
            float v10 = 16384.f * (float)accA[ma][nb][2] + 128.f * (float)accB[ma][nb][2];
            float v11 = 16384.f * (float)accA[ma][nb][3] + 128.f * (float)accB[ma][nb][3];
            float* p = C + (size_t)r0 * N_ + col;
            *(float2*)p = make_float2(sa0 * sb0 * v00 + b0, sa0 * sb1 * v01 + b1);
            *(float2*)(p + 8 * (size_t)N_) =
                make_float2(sa1 * sb0 * v10 + b0, sa1 * sb1 * v11 + b1);
        }
    }
}

// ───────── per-token 16×16 attention + softmax + q-sum + shuffle ─────────
__global__ __launch_bounds__(256) void attn_kernel(
    const float* __restrict__ qb, const float* __restrict__ kb,
    const float* __restrict__ vb, float* __restrict__ z)
{
    __shared__ float sk[HH][66];
    __shared__ float sv[HH][66];
    __shared__ float sq[QQ][HH][66];
    __shared__ float ss[QQ*HH][HH + 1];
    __shared__ float sp_[QQ*HH][HH + 1];

    const int n   = blockIdx.x;
    const int b   = n >> 11;
    const int sp  = n & 2047;
    const int tid = threadIdx.x;

    {
        const float4* kv4 = (const float4*)(kb + (size_t)n * EE);
        const float4* vv4 = (const float4*)(vb + (size_t)n * EE);
        int r = tid >> 4, c4 = (tid & 15) * 4;
        float4 kf = kv4[tid], vf = vv4[tid];
        sk[r][c4] = kf.x; sk[r][c4+1] = kf.y; sk[r][c4+2] = kf.z; sk[r][c4+3] = kf.w;
        sv[r][c4] = vf.x; sv[r][c4+1] = vf.y; sv[r][c4+2] = vf.z; sv[r][c4+3] = vf.w;
        const float4* q4 = (const float4*)(qb + (size_t)n * (QQ * EE));
        #pragma unroll
        for (int j = 0; j < 4; j++) {
            int idx = tid + j * 256;
            int qi = idx >> 8, rr = (idx >> 4) & 15, cc = (idx & 15) * 4;
            float4 qf = q4[idx];
            sq[qi][rr][cc]   = qf.x; sq[qi][rr][cc+1] = qf.y;
            sq[qi][rr][cc+2] = qf.z; sq[qi][rr][cc+3] = qf.w;
        }
    }
    __syncthreads();

    {
        const int h = tid >> 4, g = tid & 15;
        const float2* kr = (const float2*)&sk[g][0];
        #pragma unroll
        for (int qi = 0; qi < QQ; qi++) {
            const float2* qr = (const float2*)&sq[qi][h][0];
            float s = 0.f;
            #pragma unroll
            for (int dd = 0; dd < 32; dd++) {
                float2 a = qr[dd], c = kr[dd];
                s += a.x * c.x + a.y * c.y;
            }
            ss[qi * HH + h][g] = s * 0.125f;
        }
    }
    __syncthreads();

    if (tid < QQ * HH) {
        float m = -1e30f;
        #pragma unroll
        for (int g = 0; g < HH; g++) m = fmaxf(m, ss[tid][g]);
        float e[HH], sum = 0.f;
        #pragma unroll
        for (int g = 0; g < HH; g++) { e[g] = __expf(ss[tid][g] - m); sum += e[g]; }
        float inv = 1.f / sum;
        #pragma unroll
        for (int g = 0; g < HH; g++) sp_[tid][g] = e[g] * inv;
    }
    __syncthreads();

    const int d  = tid & 63;
    const int hq = tid >> 6;
    #pragma unroll
    for (int j = 0; j < 4; j++) {
        int h = hq * 4 + j;
        float o = 0.f;
        #pragma unroll
        for (int qi = 0; qi < QQ; qi++) {
            const float* pr = sp_[qi * HH + h];
            #pragma unroll
            for (int g = 0; g < HH; g++) o += pr[g] * sv[g][d];
        }
        int sfin = h * 128 + (sp >> 4);
        int e    = ((sp & 15) << 6) + d;
        z[((size_t)b * SS + sfin) * EE + e] = o;
    }
}

// ───────── host: TMA descriptor builder (uint8 rows of K=1024 bytes) ─────────
typedef CUresult (*PFN_encode)(
    CUtensorMap*, CUtensorMapDataType, cuuint32_t, void*,
    const cuuint64_t*, const cuuint64_t*, const cuuint32_t*, const cuuint32_t*,
    CUtensorMapInterleave, CUtensorMapSwizzle, CUtensorMapL2promotion,
    CUtensorMapFloatOOBfill);

static CUtensorMap mk_map8(PFN_encode enc, void* base, u64 rows, u32 boxrows) {
    CUtensorMap m;
    cuuint64_t dims[2]    = {(cuuint64_t)EE, rows};
    cuuint64_t strides[1] = {(cuuint64_t)EE};
    cuuint32_t box[2]     = {128u, boxrows};
    cuuint32_t es[2]      = {1u, 1u};
    enc(&m, CU_TENSOR_MAP_DATA_TYPE_UINT8, 2, base, dims, strides, box, es,
        CU_TENSOR_MAP_INTERLEAVE_NONE, CU_TENSOR_MAP_SWIZZLE_128B,
        CU_TENSOR_MAP_L2_PROMOTION_L2_128B, CU_TENSOR_MAP_FLOAT_OOB_FILL_NONE);
    return m;
}

extern "C" void kernel_launch(void* const* d_in, const int* in_sizes, int n_in,
                              void* d_out, int out_size)
{
    const float* x  = (const float*)d_in[0];
    const float* Wq = (const float*)d_in[1];
    const float* bq = (const float*)d_in[2];
    const float* Wk = (const float*)d_in[3];
    const float* bk = (const float*)d_in[4];
    const float* Wv = (const float*)d_in[5];
    const float* bv = (const float*)d_in[6];
    const float* Wo = (const float*)d_in[7];
    const float* bo = (const float*)d_in[8];
    float* out = (float*)d_out;

    float *pq, *pk, *pv, *pz;
    i8 *xhi, *xlo, *zhi, *zlo, *wqhi, *wqlo, *wkhi, *wklo, *wvhi, *wvlo, *wohi, *wolo;
    float *sx, *sz, *swq, *swk, *swv, *swo;
    cudaGetSymbolAddress((void**)&pq, g_q);
    cudaGetSymbolAddress((void**)&pk, g_k);
    cudaGetSymbolAddress((void**)&pv, g_v);
    cudaGetSymbolAddress((void**)&pz, g_z);
    cudaGetSymbolAddress((void**)&xhi, g_xhi);  cudaGetSymbolAddress((void**)&xlo, g_xlo);
    cudaGetSymbolAddress((void**)&zhi, g_zhi);  cudaGetSymbolAddress((void**)&zlo, g_zlo);
    cudaGetSymbolAddress((void**)&wqhi, g_wqhi); cudaGetSymbolAddress((void**)&wqlo, g_wqlo);
    cudaGetSymbolAddress((void**)&wkhi, g_wkhi); cudaGetSymbolAddress((void**)&wklo, g_wklo);
    cudaGetSymbolAddress((void**)&wvhi, g_wvhi); cudaGetSymbolAddress((void**)&wvlo, g_wvlo);
    cudaGetSymbolAddress((void**)&wohi, g_wohi); cudaGetSymbolAddress((void**)&wolo, g_wolo);
    cudaGetSymbolAddress((void**)&sx,  g_sx);   cudaGetSymbolAddress((void**)&sz,  g_sz);
    cudaGetSymbolAddress((void**)&swq, g_swq);  cudaGetSymbolAddress((void**)&swk, g_swk);
    cudaGetSymbolAddress((void**)&swv, g_swv);  cudaGetSymbolAddress((void**)&swo, g_swo);

    PFN_encode enc = 0;
    cudaDriverEntryPointQueryResult qr;
    cudaGetDriverEntryPoint("cuTensorMapEncodeTiled", (void**)&enc,
                            cudaEnableDefault, &qr);

    CUtensorMap mXh = mk_map8(enc, xhi, MM, 128);
    CUtensorMap mXl = mk_map8(enc, xlo, MM, 128);
    CUtensorMap mZh = mk_map8(enc, zhi, MM, 128);
    CUtensorMap mZl = mk_map8(enc, zlo, MM, 128);
    CUtensorMap mQh = mk_map8(enc, wqhi, (u64)QQ * EE, 256);
    CUtensorMap mQl = mk_map8(enc, wqlo, (u64)QQ * EE, 256);
    CUtensorMap mKh = mk_map8(enc, wkhi, EE, 256);
    CUtensorMap mKl = mk_map8(enc, wklo, EE, 256);
    CUtensorMap mVh = mk_map8(enc, wvhi, EE, 256);
    CUtensorMap mVl = mk_map8(enc, wvlo, EE, 256);
    CUtensorMap mOh = mk_map8(enc, wohi, EE, 256);
    CUtensorMap mOl = mk_map8(enc, wolo, EE, 256);

    cudaFuncSetAttribute(igemm, cudaFuncAttributeMaxDynamicSharedMemorySize, GSMEM);

    dim3 blk(256);
    dim3 blkG(512);
    rowquant<<<MM, blk>>>(x,  xhi,  xlo,  sx);
    rowquant<<<QQ*EE, blk>>>(Wq, wqhi, wqlo, swq);
    rowquant<<<EE, blk>>>(Wk, wkhi, wklo, swk);
    rowquant<<<EE, blk>>>(Wv, wvhi, wvlo, swv);
    rowquant<<<EE, blk>>>(Wo, wohi, wolo, swo);

    igemm<<<dim3(QQ*EE/256, MM/128), blkG, GSMEM>>>(mXh, mXl, mQh, mQl, sx, swq, bq, pq, MM, QQ*EE, EE);
    igemm<<<dim3(EE/256,    MM/128), blkG, GSMEM>>>(mXh, mXl, mKh, mKl, sx, swk, bk, pk, MM, EE, EE);
    igemm<<<dim3(EE/256,    MM/128), blkG, GSMEM>>>(mXh, mXl, mVh, mVl, sx, swv, bv, pv, MM, EE, EE);

    attn_kernel<<<MM, blk>>>(pq, pk, pv, pz);
    rowquant<<<MM, blk>>>(pz, zhi, zlo, sz);

    igemm<<<dim3(EE/256, MM/128), blkG, GSMEM>>>(mZh, mZl, mOh, mOl, sz, swo, bo, out, MM, EE, EE);
}

// round 8
// speedup vs baseline: 4.0235x; 4.0235x over previous
#include <cuda_runtime.h>
#include <cuda.h>
#include <cuda_fp16.h>

typedef unsigned int u32;
typedef unsigned long long u64;

#define BB 4
#define SS 2048
#define EE 1024
#define HH 16
#define DD 64
#define QQ 4
#define MM (BB*SS)   /* 8192 tokens */

// ───────── scratch (allocation-free rule: __device__ globals) ─────────
__device__ float g_q[(size_t)MM * (QQ*EE)];
__device__ float g_k[(size_t)MM * EE];
__device__ float g_v[(size_t)MM * EE];

__device__ __half g_xh[(size_t)MM*EE],  g_xl[(size_t)MM*EE];
__device__ __half g_zh[(size_t)MM*EE],  g_zl[(size_t)MM*EE];
__device__ __half g_wq[(size_t)QQ*EE*EE];
__device__ __half g_wk[(size_t)EE*EE];
__device__ __half g_wv[(size_t)EE*EE];
__device__ __half g_wo[(size_t)EE*EE];

__device__ __forceinline__ u32 smem_u32(const void* p) {
    u32 a;
    asm("{ .reg .u64 t; cvta.to.shared.u64 t, %1; cvt.u32.u64 %0, t; }"
        : "=r"(a) : "l"(p));
    return a;
}
__device__ __forceinline__ void ldsm4(u32 addr, u32* r) {
    asm volatile("ldmatrix.sync.aligned.m8n8.x4.shared.b16 {%0,%1,%2,%3}, [%4];"
                 : "=r"(r[0]), "=r"(r[1]), "=r"(r[2]), "=r"(r[3]) : "r"(addr));
}
__device__ __forceinline__ void mma16816(float* c, const u32* a, const u32* b) {
    asm volatile(
        "mma.sync.aligned.m16n8k16.row.col.f32.f16.f16.f32 "
        "{%0,%1,%2,%3}, {%4,%5,%6,%7}, {%8,%9}, {%0,%1,%2,%3};"
        : "+f"(c[0]), "+f"(c[1]), "+f"(c[2]), "+f"(c[3])
        : "r"(a[0]), "r"(a[1]), "r"(a[2]), "r"(a[3]), "r"(b[0]), "r"(b[1]));
}
__device__ __forceinline__ void tma2d(u32 saddr, const CUtensorMap* m,
                                      int cx, int cy, u32 mbar) {
    asm volatile(
        "cp.async.bulk.tensor.2d.shared::cta.global.tile.mbarrier::complete_tx::bytes "
        "[%0], [%1, {%2, %3}], [%4];"
        :: "r"(saddr), "l"(m), "r"(cx), "r"(cy), "r"(mbar) : "memory");
}
#define MBAR_INIT(addr, cnt) \
    asm volatile("mbarrier.init.shared.b64 [%0], %1;" :: "r"(addr), "r"(cnt) : "memory")
#define MBAR_EXPECT(addr, bytes) \
    asm volatile("mbarrier.arrive.expect_tx.shared.b64 _, [%0], %1;" \
                 :: "r"(addr), "r"(bytes) : "memory")
__device__ __forceinline__ void mbar_wait(u32 addr, u32 parity) {
    asm volatile(
        "{\n\t.reg .pred P;\n\t"
        "W%=:\n\t"
        "mbarrier.try_wait.parity.acquire.cta.shared::cta.b64 P, [%0], %1, 0x989680;\n\t"
        "@P bra D%=;\n\t"
        "bra W%=;\n\t"
        "D%=:\n\t}"
        :: "r"(addr), "r"(parity) : "memory");
}
#define SWZ(off) ((u32)(off) ^ ((((u32)(off)) >> 3) & 0x70))

// ───────── fp32 → fp16 hi/lo split (activation side) ─────────
__global__ __launch_bounds__(256) void split16(
    const float* __restrict__ s, __half* __restrict__ h,
    __half* __restrict__ l, int n4)
{
    int i = blockIdx.x * blockDim.x + threadIdx.x;
    if (i >= n4) return;
    float4 v = ((const float4*)s)[i];
    float f[4] = {v.x, v.y, v.z, v.w};
    ushort4 ho, lo;
    unsigned short* hp = &ho.x; unsigned short* lp = &lo.x;
    #pragma unroll
    for (int j = 0; j < 4; j++) {
        __half hb = __float2half_rn(f[j]);
        __half lb = __float2half_rn(f[j] - __half2float(hb));
        hp[j] = __half_as_ushort(hb);
        lp[j] = __half_as_ushort(lb);
    }
    ((ushort4*)h)[i] = ho;
    ((ushort4*)l)[i] = lo;
}

// ───────── fp32 → fp16 (weight side, single) ─────────
__global__ __launch_bounds__(256) void conv16(
    const float* __restrict__ s, __half* __restrict__ h, int n4)
{
    int i = blockIdx.x * blockDim.x + threadIdx.x;
    if (i >= n4) return;
    float4 v = ((const float4*)s)[i];
    ushort4 ho;
    ho.x = __half_as_ushort(__float2half_rn(v.x));
    ho.y = __half_as_ushort(__float2half_rn(v.y));
    ho.z = __half_as_ushort(__float2half_rn(v.z));
    ho.w = __half_as_ushort(__float2half_rn(v.w));
    ((ushort4*)h)[i] = ho;
}

// ───────── fp16 2-pass GEMM: TMA + mma.sync ─────────
// C[M,N] = (Ah+Al)[M,K] · W16[N,K]^T + bias, fp32 accum (shared across passes).
// CTA tile 128×256, 8 warps × (64m×64n), K-chunk 64 (128B rows, SW128),
// 3-stage TMA pipeline.
#define CHK 64
#define SOFF_AH 0u
#define SOFF_AL 16384u
#define SOFF_B  32768u
#define STB 65536u                /* 64 KB per stage */
#define SM_CTRL (3u*STB)          /* mbar[3] */
#define GSMEM (3*65536 + 64)

__global__ __launch_bounds__(256, 1) void hgemm(
    const __grid_constant__ CUtensorMap tAh,
    const __grid_constant__ CUtensorMap tAl,
    const __grid_constant__ CUtensorMap tB,
    const float* __restrict__ bias, float* __restrict__ C,
    int M, int N_, int K)
{
    extern __shared__ __align__(1024) char smem[];
    const u32 sb   = smem_u32(smem);
    const int tid  = threadIdx.x;
    const int wid  = tid >> 5;
    const int lane = tid & 31;
    const int m0   = blockIdx.y * 128;
    const int n0   = blockIdx.x * 256;
    const int wm   = (wid & 1) * 64;
    const int wn   = (wid >> 1) * 64;
    const int nch  = K / CHK;         // 16

    float acc[4][8][4];
    #pragma unroll
    for (int i = 0; i < 4; i++)
        #pragma unroll
        for (int j = 0; j < 8; j++)
            #pragma unroll
            for (int t = 0; t < 4; t++) acc[i][j][t] = 0.f;

    if (tid == 0) {
        MBAR_INIT(sb + SM_CTRL, 1);
        MBAR_INIT(sb + SM_CTRL + 8, 1);
        MBAR_INIT(sb + SM_CTRL + 16, 1);
    }
    __syncthreads();

    auto issue = [&](int c) {
        if (tid == 0) {
            const int st   = c % 3;
            const u32 mbar = sb + SM_CTRL + st * 8;
            const u32 s0   = sb + st * STB;
            MBAR_EXPECT(mbar, 65536u);
            int kc = c * CHK;
            tma2d(s0 + SOFF_AH, &tAh, kc, m0, mbar);
            tma2d(s0 + SOFF_AL, &tAl, kc, m0, mbar);
            tma2d(s0 + SOFF_B,  &tB,  kc, n0, mbar);
        }
    };

    issue(0);
    issue(1);
    issue(2);

    for (int c = 0; c < nch; c++) {
        const int st = c % 3;
        mbar_wait(sb + SM_CTRL + st * 8, (c / 3) & 1);
        const u32 s0 = sb + st * STB;

        #pragma unroll
        for (int ks = 0; ks < 4; ks++) {
            const int k0 = ks * 16;
            u32 ah[4][4], al[4][4], b[4][4];
            #pragma unroll
            for (int ma = 0; ma < 4; ma++) {
                int row  = wm + ma * 16 + ((lane >> 3) & 1) * 8 + (lane & 7);
                int colB = (k0 + (lane >> 4) * 8) * 2;
                u32 off  = SWZ(row * 128 + colB);
                ldsm4(s0 + SOFF_AH + off, ah[ma]);
                ldsm4(s0 + SOFF_AL + off, al[ma]);
            }
            #pragma unroll
            for (int j = 0; j < 4; j++) {
                int row  = wn + j * 16 + (lane >> 4) * 8 + (lane & 7);
                int colB = (k0 + ((lane >> 3) & 1) * 8) * 2;
                u32 off  = SWZ(row * 128 + colB);
                ldsm4(s0 + SOFF_B + off, b[j]);
            }
            // pass 1: Ah·B   (8 independent acc slots per ma-group)
            #pragma unroll
            for (int j = 0; j < 4; j++)
                #pragma unroll
                for (int ma = 0; ma < 4; ma++) {
                    mma16816(acc[ma][j*2+0], ah[ma], &b[j][0]);
                    mma16816(acc[ma][j*2+1], ah[ma], &b[j][2]);
                }
            // pass 2: Al·B  → same accumulators (A = Ah + Al exactly)
            #pragma unroll
            for (int j = 0; j < 4; j++)
                #pragma unroll
                for (int ma = 0; ma < 4; ma++) {
                    mma16816(acc[ma][j*2+0], al[ma], &b[j][0]);
                    mma16816(acc[ma][j*2+1], al[ma], &b[j][2]);
                }
        }
        __syncthreads();               // all warps done reading stage st
        if (c + 3 < nch) issue(c + 3);
    }

    #pragma unroll
    for (int ma = 0; ma < 4; ma++) {
        #pragma unroll
        for (int nb = 0; nb < 8; nb++) {
            int row = m0 + wm + ma * 16 + (lane >> 2);
            int col = n0 + wn + nb * 8 + (lane & 3) * 2;
            float b0 = bias[col], b1 = bias[col + 1];
            float* p = C + (size_t)row * N_ + col;
            *(float2*)p = make_float2(acc[ma][nb][0] + b0, acc[ma][nb][1] + b1);
            *(float2*)(p + 8 * (size_t)N_) =
                make_float2(acc[ma][nb][2] + b0, acc[ma][nb][3] + b1);
        }
    }
}

// ───────── per-token 16×16 attention + softmax + q-sum + shuffle ─────────
// writes fp16 hi/lo z directly (feeds the O-projection GEMM's split-A side).
__global__ __launch_bounds__(256) void attn_kernel(
    const float* __restrict__ qb, const float* __restrict__ kb,
    const float* __restrict__ vb,
    __half* __restrict__ zh, __half* __restrict__ zl)
{
    __shared__ float sk[HH][66];
    __shared__ float sv[HH][66];
    __shared__ float sq[QQ][HH][66];
    __shared__ float ss[QQ*HH][HH + 1];
    __shared__ float sp_[QQ*HH][HH + 1];

    const int n   = blockIdx.x;
    const int b   = n >> 11;
    const int sp  = n & 2047;
    const int tid = threadIdx.x;

    {
        const float4* kv4 = (const float4*)(kb + (size_t)n * EE);
        const float4* vv4 = (const float4*)(vb + (size_t)n * EE);
        int r = tid >> 4, c4 = (tid & 15) * 4;
        float4 kf = kv4[tid], vf = vv4[tid];
        sk[r][c4] = kf.x; sk[r][c4+1] = kf.y; sk[r][c4+2] = kf.z; sk[r][c4+3] = kf.w;
        sv[r][c4] = vf.x; sv[r][c4+1] = vf.y; sv[r][c4+2] = vf.z; sv[r][c4+3] = vf.w;
        const float4* q4 = (const float4*)(qb + (size_t)n * (QQ * EE));
        #pragma unroll
        for (int j = 0; j < 4; j++) {
            int idx = tid + j * 256;
            int qi = idx >> 8, rr = (idx >> 4) & 15, cc = (idx & 15) * 4;
            float4 qf = q4[idx];
            sq[qi][rr][cc]   = qf.x; sq[qi][rr][cc+1] = qf.y;
            sq[qi][rr][cc+2] = qf.z; sq[qi][rr][cc+3] = qf.w;
        }
    }
    __syncthreads();

    {
        const int h = tid >> 4, g = tid & 15;
        const float2* kr = (const float2*)&sk[g][0];
        #pragma unroll
        for (int qi = 0; qi < QQ; qi++) {
            const float2* qr = (const float2*)&sq[qi][h][0];
            float s = 0.f;
            #pragma unroll
            for (int dd = 0; dd < 32; dd++) {
                float2 a = qr[dd], c = kr[dd];
                s += a.x * c.x + a.y * c.y;
            }
            ss[qi * HH + h][g] = s * 0.125f;
        }
    }
    __syncthreads();

    if (tid < QQ * HH) {
        float m = -1e30f;
        #pragma unroll
        for (int g = 0; g < HH; g++) m = fmaxf(m, ss[tid][g]);
        float e[HH], sum = 0.f;
        #pragma unroll
        for (int g = 0; g < HH; g++) { e[g] = __expf(ss[tid][g] - m); sum += e[g]; }
        float inv = 1.f / sum;
        #pragma unroll
        for (int g = 0; g < HH; g++) sp_[tid][g] = e[g] * inv;
    }
    __syncthreads();

    const int d  = tid & 63;
    const int hq = tid >> 6;
    #pragma unroll
    for (int j = 0; j < 4; j++) {
        int h = hq * 4 + j;
        float o = 0.f;
        #pragma unroll
        for (int qi = 0; qi < QQ; qi++) {
            const float* pr = sp_[qi * HH + h];
            #pragma unroll
            for (int g = 0; g < HH; g++) o += pr[g] * sv[g][d];
        }
        int sfin = h * 128 + (sp >> 4);
        int e    = ((sp & 15) << 6) + d;
        size_t idx = ((size_t)b * SS + sfin) * EE + e;
        __half hb = __float2half_rn(o);
        zh[idx] = hb;
        zl[idx] = __float2half_rn(o - __half2float(hb));
    }
}

// ───────── host: TMA descriptor builder (fp16, 64-elem = 128B box rows) ─────────
typedef CUresult (*PFN_encode)(
    CUtensorMap*, CUtensorMapDataType, cuuint32_t, void*,
    const cuuint64_t*, const cuuint64_t*, const cuuint32_t*, const cuuint32_t*,
    CUtensorMapInterleave, CUtensorMapSwizzle, CUtensorMapL2promotion,
    CUtensorMapFloatOOBfill);

static CUtensorMap mk_map16(PFN_encode enc, void* base, u64 rows, u32 boxrows) {
    CUtensorMap m;
    cuuint64_t dims[2]    = {(cuuint64_t)EE, rows};
    cuuint64_t strides[1] = {(cuuint64_t)EE * 2};
    cuuint32_t box[2]     = {64u, boxrows};
    cuuint32_t es[2]      = {1u, 1u};
    enc(&m, CU_TENSOR_MAP_DATA_TYPE_FLOAT16, 2, base, dims, strides, box, es,
        CU_TENSOR_MAP_INTERLEAVE_NONE, CU_TENSOR_MAP_SWIZZLE_128B,
        CU_TENSOR_MAP_L2_PROMOTION_L2_128B, CU_TENSOR_MAP_FLOAT_OOB_FILL_NONE);
    return m;
}

extern "C" void kernel_launch(void* const* d_in, const int* in_sizes, int n_in,
                              void* d_out, int out_size)
{
    const float* x  = (const float*)d_in[0];
    const float* Wq = (const float*)d_in[1];
    const float* bq = (const float*)d_in[2];
    const float* Wk = (const float*)d_in[3];
    const float* bk = (const float*)d_in[4];
    const float* Wv = (const float*)d_in[5];
    const float* bv = (const float*)d_in[6];
    const float* Wo = (const float*)d_in[7];
    const float* bo = (const float*)d_in[8];
    float* out = (float*)d_out;

    float *pq, *pk, *pv;
    __half *xh, *xl, *zh, *zl, *wq, *wk, *wv, *wo;
    cudaGetSymbolAddress((void**)&pq, g_q);
    cudaGetSymbolAddress((void**)&pk, g_k);
    cudaGetSymbolAddress((void**)&pv, g_v);
    cudaGetSymbolAddress((void**)&xh, g_xh);  cudaGetSymbolAddress((void**)&xl, g_xl);
    cudaGetSymbolAddress((void**)&zh, g_zh);  cudaGetSymbolAddress((void**)&zl, g_zl);
    cudaGetSymbolAddress((void**)&wq, g_wq);  cudaGetSymbolAddress((void**)&wk, g_wk);
    cudaGetSymbolAddress((void**)&wv, g_wv);  cudaGetSymbolAddress((void**)&wo, g_wo);

    PFN_encode enc = 0;
    cudaDriverEntryPointQueryResult qr;
    cudaGetDriverEntryPoint("cuTensorMapEncodeTiled", (void**)&enc,
                            cudaEnableDefault, &qr);

    CUtensorMap mXh = mk_map16(enc, xh, MM, 128);
    CUtensorMap mXl = mk_map16(enc, xl, MM, 128);
    CUtensorMap mZh = mk_map16(enc, zh, MM, 128);
    CUtensorMap mZl = mk_map16(enc, zl, MM, 128);
    CUtensorMap mQ  = mk_map16(enc, wq, (u64)QQ * EE, 256);
    CUtensorMap mK  = mk_map16(enc, wk, EE, 256);
    CUtensorMap mV  = mk_map16(enc, wv, EE, 256);
    CUtensorMap mO  = mk_map16(enc, wo, EE, 256);

    cudaFuncSetAttribute(hgemm, cudaFuncAttributeMaxDynamicSharedMemorySize, GSMEM);

    dim3 blk(256);
    split16<<<(MM*EE/4 + 255)/256, blk>>>(x, xh, xl, MM*EE/4);
    conv16<<<(QQ*EE*EE/4 + 255)/256, blk>>>(Wq, wq, QQ*EE*EE/4);
    conv16<<<(EE*EE/4 + 255)/256, blk>>>(Wk, wk, EE*EE/4);
    conv16<<<(EE*EE/4 + 255)/256, blk>>>(Wv, wv, EE*EE/4);
    conv16<<<(EE*EE/4 + 255)/256, blk>>>(Wo, wo, EE*EE/4);

    hgemm<<<dim3(QQ*EE/256, MM/128), blk, GSMEM>>>(mXh, mXl, mQ, bq, pq, MM, QQ*EE, EE);
    hgemm<<<dim3(EE/256,    MM/128), blk, GSMEM>>>(mXh, mXl, mK, bk, pk, MM, EE, EE);
    hgemm<<<dim3(EE/256,    MM/128), blk, GSMEM>>>(mXh, mXl, mV, bv, pv, MM, EE, EE);

    attn_kernel<<<MM, blk>>>(pq, pk, pv, zh, zl);

    hgemm<<<dim3(EE/256, MM/128), blk, GSMEM>>>(mZh, mZl, mO, bo, out, MM, EE, EE);
}